// round 16
// baseline (speedup 1.0000x reference)
#include <cuda_runtime.h>
#include <math.h>

#define NB 2048
#define BN_EPS 1e-5

// ---- fp64 stats (encoder + loss) ----
#define ST1_SUM 0     // 16
#define ST1_SQ  16    // 16
#define ST2_SUM 32    // 2
#define ST2_SQ  34    // 2
#define ST_LOSS 36
#define ST_TOTAL 37
// ---- fp32 stats (decoder) ----
#define FH1_SUM 0   // 2
#define FH1_SQ  2   // 2
#define FH2_SUM 4   // 2
#define FH2_SQ  6   // 2
#define FY3_SUM 8   // 32
#define FY3_SQ  40  // 32
#define STF_TOTAL 72

__device__ double g_stats[ST_TOTAL];
__device__ float g_statsf[STF_TOTAL];
__device__ float g_y1[NB * 16 * 196];   // conv1 raw out (B,16,14,14)
__device__ float g_y2[NB * 98];         // conv2 raw out (B,2,7,7)
__device__ float g_h1[NB * 98];         // dec conv1 raw out
__device__ float g_h2[NB * 98];         // dec conv2 raw out
__device__ float g_y3[NB * 32 * 196];   // convT1 raw out (B,32,14,14) channel-major

// decoder BN coefficients from fp32 sums
__device__ __forceinline__ void bn_coef_f(float sum, float sq, double N,
                                          float g, float b, float* sc, float* sh) {
    double mu = (double)sum / N;
    double var = (double)sq / N - mu * mu;
    double s = (double)g / sqrt(var + BN_EPS);
    *sc = (float)s;
    *sh = (float)((double)b - mu * s);
}

// encoder BN: fp32 mu / var rounded once from exact fp64 stats; r via libdevice rsqrtf
__device__ __forceinline__ void bn_mur(double sum, double sq, double N,
                                       float* muf, float* rf) {
    double mu = sum / N;
    double var = sq / N - mu * mu;
    float vf = (float)var;
    *muf = (float)mu;
    *rf = rsqrtf(__fadd_rn(vf, 1e-5f));
}

// exact reference BN+ReLU: relu(((x - mu) * r) * g + b)
__device__ __forceinline__ float bn_ref(float x, float mu, float r, float g, float b) {
    float t = __fmul_rn(__fsub_rn(x, mu), r);
    return fmaxf(__fmaf_rn(t, g, b), 0.f);
}

// ---------------- K0: zero stats ----------------
__global__ void k0_zero() {
    int t = threadIdx.x;
    if (t < ST_TOTAL) g_stats[t] = 0.0;
    if (t < STF_TOTAL) g_statsf[t] = 0.f;
}

// ---------------- K1: conv1 (1->16, 4x4, s2, p1), fp64-exact accumulation + fp64 stats ----------------
__global__ void __launch_bounds__(224) k1_conv1(const float* __restrict__ x,
                                                const float* __restrict__ w,
                                                const float* __restrict__ bias) {
    __shared__ float sx[784];
    __shared__ float sw[256];
    __shared__ float sb[16];
    __shared__ float ys[16 * 196];
    __shared__ double sA[16], sQ[16];
    int b = blockIdx.x, t = threadIdx.x;

    // all inputs; conv work does NOT depend on k0 (only the final stats atomics do)
    for (int i = t; i < 784; i += 224) sx[i] = x[b * 784 + i];
    for (int i = t; i < 256; i += 224) sw[i] = w[i];
    if (t < 16) { sb[t] = bias[t]; sA[t] = 0.0; sQ[t] = 0.0; }
    __syncthreads();

    bool act = t < 196;
    int oy = act ? t / 14 : 0, ox = act ? t % 14 : 0;
    float win[16];
#pragma unroll
    for (int k = 0; k < 16; k++) win[k] = 0.f;
    if (act) {
#pragma unroll
        for (int ky = 0; ky < 4; ky++) {
            int iy = 2 * oy - 1 + ky;
#pragma unroll
            for (int kx = 0; kx < 4; kx++) {
                int ix = 2 * ox - 1 + kx;
                win[ky * 4 + kx] = (iy >= 0 && iy < 28 && ix >= 0 && ix < 28) ? sx[iy * 28 + ix] : 0.f;
            }
        }
    }
    if (act) {
        double dwin[16];
#pragma unroll
        for (int k = 0; k < 16; k++) dwin[k] = (double)win[k];
#pragma unroll
        for (int c = 0; c < 16; c++) {
            double s = 0.0;
#pragma unroll
            for (int k = 0; k < 16; k++) s = fma(dwin[k], (double)sw[c * 16 + k], s);
            float v = __fadd_rn((float)s, sb[c]);
            g_y1[(b * 16 + c) * 196 + t] = v;
            ys[c * 196 + t] = v;
        }
    }
    __syncthreads();

    {
        int ch = t / 14, sub = t % 14;
        const float* row = &ys[ch * 196 + sub * 14];
        double s = 0.0, s2 = 0.0;
#pragma unroll
        for (int i = 0; i < 14; i++) { double v = (double)row[i]; s += v; s2 = fma(v, v, s2); }
        atomicAdd(&sA[ch], s); atomicAdd(&sQ[ch], s2);
    }
    __syncthreads();
    cudaGridDependencySynchronize();   // k0's zeroing must be visible for global atomics
    if (t < 16) {
        atomicAdd(&g_stats[ST1_SUM + t], sA[t]);
        atomicAdd(&g_stats[ST1_SQ + t], sQ[t]);
    }
}

// ---------------- K2: BN1+ReLU -> conv2 (16->2) fp64-exact, split 2-way + fp64 stats ----------------
__global__ void __launch_bounds__(224) k2_conv2(const float* __restrict__ w2,
                                                const float* __restrict__ bias2,
                                                const float* __restrict__ g1,
                                                const float* __restrict__ b1) {
    __shared__ float s1[3136];
    __shared__ float sw[512];
    __shared__ float smu[16], sr[16], sg[16], sbb[16];
    __shared__ double psd[196];
    __shared__ double sA[2], sQ[2];
    int b = blockIdx.x, t = threadIdx.x;

    // input-only staging overlaps predecessor tail
    for (int i = t; i < 512; i += 224) sw[i] = w2[i];
    if (t < 2) { sA[t] = 0.0; sQ[t] = 0.0; }
    cudaGridDependencySynchronize();   // g_stats / g_y1 now valid

    if (t < 16) {
        bn_mur(g_stats[ST1_SUM + t], g_stats[ST1_SQ + t], 401408.0, &smu[t], &sr[t]);
        sg[t] = g1[t]; sbb[t] = b1[t];
    }
    __syncthreads();

    for (int i = t; i < 3136; i += 224) {
        int c = i / 196;
        s1[i] = bn_ref(g_y1[b * 3136 + i], smu[c], sr[c], sg[c], sbb[c]);
    }
    __syncthreads();

    if (t < 196) {
        int half = t / 98, o = t % 98;
        int c = o / 49, p = o % 49, oy = p / 7, ox = p % 7;
        double s = 0.0;
#pragma unroll
        for (int ic8 = 0; ic8 < 8; ic8++) {
            int ic = half * 8 + ic8;
#pragma unroll
            for (int ky = 0; ky < 4; ky++) {
                int iy = 2 * oy - 1 + ky;
                if (iy < 0 || iy >= 14) continue;
#pragma unroll
                for (int kx = 0; kx < 4; kx++) {
                    int ix = 2 * ox - 1 + kx;
                    if (ix < 0 || ix >= 14) continue;
                    s = fma((double)s1[ic * 196 + iy * 14 + ix],
                            (double)sw[c * 256 + ic * 16 + ky * 4 + kx], s);
                }
            }
        }
        psd[t] = s;
    }
    __syncthreads();

    if (t < 98) {
        int c = t / 49;
        double sum = psd[t] + psd[t + 98];
        float v = __fadd_rn((float)sum, bias2[c]);
        g_y2[b * 98 + t] = v;
        atomicAdd(&sA[c], (double)v); atomicAdd(&sQ[c], (double)v * (double)v);
    }
    __syncthreads();
    if (t < 2) {
        atomicAdd(&g_stats[ST2_SUM + t], sA[t]);
        atomicAdd(&g_stats[ST2_SQ + t], sQ[t]);
    }
}

// ------- K3: BN2+ReLU -> VQ (float4 codebook, interleaved 4-way k split) -> dec conv1 + fp32 stats -------
__global__ void __launch_bounds__(256) k3_vq(const float* __restrict__ embed,
                                             const float* __restrict__ g2,
                                             const float* __restrict__ b2,
                                             const float* __restrict__ dw1,
                                             const float* __restrict__ dbi1,
                                             float* __restrict__ cls) {
    __shared__ float4 se4[512];
    __shared__ float sq[98], qt[98];
    __shared__ float smu[2], sr[2], sg[2], sbb[2];
    __shared__ float bd[196];
    __shared__ int bidx[196];
    __shared__ float sAf[2], sQf[2];
    __shared__ double sloss;
    int b = blockIdx.x, t = threadIdx.x;

    // codebook staging (input-only) overlaps predecessor tail
    const float2* emb2 = (const float2*)embed;
    for (int k = t; k < 512; k += 256) {
        float2 e = emb2[k];
        float ee = __fadd_rn(__fmul_rn(e.x, e.x), __fmul_rn(e.y, e.y));
        se4[k] = make_float4(e.x, e.y, ee, 0.f);
    }
    if (t == 2) sloss = 0.0;
    cudaGridDependencySynchronize();   // g_stats / g_y2 now valid

    if (t < 2) {
        bn_mur(g_stats[ST2_SUM + t], g_stats[ST2_SQ + t], 100352.0, &smu[t], &sr[t]);
        sg[t] = g2[t]; sbb[t] = b2[t];
        sAf[t] = 0.f; sQf[t] = 0.f;
    }
    __syncthreads();   // BN coefs + codebook visible to all

    if (t < 98) {
        int c = t / 49;
        sq[t] = bn_ref(g_y2[b * 98 + t], smu[c], sr[c], sg[c], sbb[c]);
    }
    __syncthreads();

    if (t < 196) {
        int n = t >> 2, ch = t & 3;
        float q0 = sq[2 * n], q1 = sq[2 * n + 1];
        float qq = __fadd_rn(__fmul_rn(q0, q0), __fmul_rn(q1, q1));
        float best = 3.4e38f; int bi = ch;
#pragma unroll 4
        for (int j = 0; j < 128; j++) {
            int k = ch + 4 * j;
            float4 E = se4[k];
            float dot = __fmaf_rn(q1, E.y, __fmul_rn(q0, E.x));
            float d = __fsub_rn(__fadd_rn(qq, E.z), __fmul_rn(2.f, dot));
            if (d < best) { best = d; bi = k; }
        }
        bd[t] = best; bidx[t] = bi;
    }
    __syncthreads();

    if (t < 49) {
        float best = bd[4 * t]; int k = bidx[4 * t];
#pragma unroll
        for (int j = 1; j < 4; j++) {
            float d = bd[4 * t + j]; int kk = bidx[4 * t + j];
            if (d < best || (d == best && kk < k)) { best = d; k = kk; }
        }
        float4 E = se4[k];
        qt[2 * t] = E.x; qt[2 * t + 1] = E.y;
        if (cls) cls[b * 49 + t] = (float)k;
        float da = E.x - sq[2 * t], db = E.y - sq[2 * t + 1];
        atomicAdd(&sloss, (double)da * da + (double)db * db);
    }
    __syncthreads();

    if (t < 98) {
        int o = t / 49, p = t % 49;
        float v = fmaf(dw1[o * 2], qt[p], fmaf(dw1[o * 2 + 1], qt[49 + p], dbi1[o]));
        g_h1[b * 98 + t] = v;
        atomicAdd(&sAf[o], v); atomicAdd(&sQf[o], v * v);
    }
    __syncthreads();
    if (t < 2) {
        atomicAdd(&g_statsf[FH1_SUM + t], sAf[t]);
        atomicAdd(&g_statsf[FH1_SQ + t], sQf[t]);
    }
    if (t == 2) atomicAdd(&g_stats[ST_LOSS], sloss);
}

// ---------------- K4: BN(h1)+ReLU -> dec conv2 (1x1) + fp32 stats ----------------
__global__ void __launch_bounds__(128) k4_dec2(const float* __restrict__ dg1,
                                               const float* __restrict__ dbb1,
                                               const float* __restrict__ dw2,
                                               const float* __restrict__ dbi2) {
    __shared__ float hb[98];
    __shared__ float sc[2], sh[2], sAf[2], sQf[2];
    int b = blockIdx.x, t = threadIdx.x;
    cudaGridDependencySynchronize();   // g_statsf / g_h1 now valid
    if (t < 2) {
        bn_coef_f(g_statsf[FH1_SUM + t], g_statsf[FH1_SQ + t], 100352.0,
                  dg1[t], dbb1[t], &sc[t], &sh[t]);
        sAf[t] = 0.f; sQf[t] = 0.f;
    }
    __syncthreads();
    if (t < 98) {
        int c = t / 49;
        hb[t] = fmaxf(fmaf(g_h1[b * 98 + t], sc[c], sh[c]), 0.f);
    }
    __syncthreads();
    if (t < 98) {
        int o = t / 49, p = t % 49;
        float v = fmaf(dw2[o * 2], hb[p], fmaf(dw2[o * 2 + 1], hb[49 + p], dbi2[o]));
        g_h2[b * 98 + t] = v;
        atomicAdd(&sAf[o], v); atomicAdd(&sQf[o], v * v);
    }
    __syncthreads();
    if (t < 2) {
        atomicAdd(&g_statsf[FH2_SUM + t], sAf[t]);
        atomicAdd(&g_statsf[FH2_SQ + t], sQf[t]);
    }
}

// ---------------- K5: BN(h2)+ReLU -> convT1 (2->32) + smem-staged fp32 stats ----------------
__global__ void __launch_bounds__(224) k5_convt1(const float* __restrict__ dg2,
                                                 const float* __restrict__ dbb2,
                                                 const float* __restrict__ tw1,
                                                 const float* __restrict__ tbi1) {
    __shared__ float si[98];
    __shared__ float sw[1024];
    __shared__ float sc[2], sh[2];
    __shared__ float ys[32 * 196];
    __shared__ float sAf[32], sQf[32];
    __shared__ float sb[32];
    int b = blockIdx.x, t = threadIdx.x;

    // input-only staging overlaps predecessor tail
    for (int i = t; i < 1024; i += 224) sw[i] = tw1[i];
    if (t < 32) { sAf[t] = 0.f; sQf[t] = 0.f; sb[t] = tbi1[t]; }
    cudaGridDependencySynchronize();   // g_statsf / g_h2 now valid

    if (t < 2) {
        bn_coef_f(g_statsf[FH2_SUM + t], g_statsf[FH2_SQ + t], 100352.0,
                  dg2[t], dbb2[t], &sc[t], &sh[t]);
    }
    __syncthreads();
    for (int i = t; i < 98; i += 224) {
        int c = i / 49;
        si[i] = fmaxf(fmaf(g_h2[b * 98 + i], sc[c], sh[c]), 0.f);
    }
    __syncthreads();

    if (t < 196) {
        int y = t / 14, x = t % 14;
        int pary = (y + 1) & 1, parx = (x + 1) & 1;
        int iya = (y + 1 - pary) >> 1, iyb = iya - 1;
        int ixa = (x + 1 - parx) >> 1, ixb = ixa - 1;
        bool vya = (iya < 7), vyb = (iyb >= 0);
        bool vxa = (ixa < 7), vxb = (ixb >= 0);
        int kk_aa = pary * 4 + parx,       off_aa = iya * 7 + ixa;
        int kk_ab = pary * 4 + parx + 2,   off_ab = iya * 7 + ixb;
        int kk_ba = (pary + 2) * 4 + parx, off_ba = iyb * 7 + ixa;
        int kk_bb = (pary + 2) * 4 + parx + 2, off_bb = iyb * 7 + ixb;
        bool c_aa = vya && vxa, c_ab = vya && vxb, c_ba = vyb && vxa, c_bb = vyb && vxb;

#pragma unroll 4
        for (int o = 0; o < 32; o++) {
            float v = sb[o];
            if (c_aa) { v = fmaf(si[off_aa], sw[o * 16 + kk_aa], v); v = fmaf(si[49 + off_aa], sw[512 + o * 16 + kk_aa], v); }
            if (c_ab) { v = fmaf(si[off_ab], sw[o * 16 + kk_ab], v); v = fmaf(si[49 + off_ab], sw[512 + o * 16 + kk_ab], v); }
            if (c_ba) { v = fmaf(si[off_ba], sw[o * 16 + kk_ba], v); v = fmaf(si[49 + off_ba], sw[512 + o * 16 + kk_ba], v); }
            if (c_bb) { v = fmaf(si[off_bb], sw[o * 16 + kk_bb], v); v = fmaf(si[49 + off_bb], sw[512 + o * 16 + kk_bb], v); }
            g_y3[(b * 32 + o) * 196 + t] = v;
            ys[o * 196 + t] = v;
        }
    }
    __syncthreads();

    {
        int ch = t / 7, sub = t % 7;
        float s = 0.f, s2 = 0.f;
        const float* row = &ys[ch * 196 + sub * 28];
#pragma unroll
        for (int i = 0; i < 28; i++) { float v = row[i]; s += v; s2 = fmaf(v, v, s2); }
        atomicAdd(&sAf[ch], s); atomicAdd(&sQf[ch], s2);
    }
    __syncthreads();
    if (t < 32) {
        atomicAdd(&g_statsf[FY3_SUM + t], sAf[t]);
        atomicAdd(&g_statsf[FY3_SQ + t], sQf[t]);
    }
}

// ---------------- K6: BN(y3)+ReLU -> convT2 (32->1) -> fast sigmoid ----------------
__global__ void __launch_bounds__(256) k6_convt2(const float* __restrict__ dg3,
                                                 const float* __restrict__ dbb3,
                                                 const float* __restrict__ tw2,
                                                 const float* __restrict__ tbi2,
                                                 float* __restrict__ outp,
                                                 float* __restrict__ lossp) {
    __shared__ float si[6272];
    __shared__ float sw[512];
    __shared__ float sc[32], sh[32];
    int b = blockIdx.x, t = threadIdx.x;

    // input-only staging overlaps predecessor tail
    for (int i = t; i < 512; i += 256) sw[i] = tw2[i];
    cudaGridDependencySynchronize();   // g_statsf / g_y3 / g_stats[ST_LOSS] now valid

    if (t < 32) {
        bn_coef_f(g_statsf[FY3_SUM + t], g_statsf[FY3_SQ + t], 401408.0,
                  dg3[t], dbb3[t], &sc[t], &sh[t]);
    }
    __syncthreads();
    for (int i = t; i < 6272; i += 256) {
        int c = i / 196;
        si[i] = fmaxf(fmaf(g_y3[b * 6272 + i], sc[c], sh[c]), 0.f);
    }
    __syncthreads();

    float bias = tbi2[0];
    for (int idx = t; idx < 784; idx += 256) {
        int y = idx / 28, x = idx % 28;
        int pary = (y + 1) & 1, parx = (x + 1) & 1;
        int iya = (y + 1 - pary) >> 1, iyb = iya - 1;
        int ixa = (x + 1 - parx) >> 1, ixb = ixa - 1;
        bool vya = iya < 14, vyb = iyb >= 0, vxa = ixa < 14, vxb = ixb >= 0;
        float v = bias;
        if (vya && vxa) { int off = iya * 14 + ixa, kk = pary * 4 + parx;
#pragma unroll
            for (int i = 0; i < 32; i++) v = fmaf(si[i * 196 + off], sw[i * 16 + kk], v); }
        if (vya && vxb) { int off = iya * 14 + ixb, kk = pary * 4 + parx + 2;
#pragma unroll
            for (int i = 0; i < 32; i++) v = fmaf(si[i * 196 + off], sw[i * 16 + kk], v); }
        if (vyb && vxa) { int off = iyb * 14 + ixa, kk = (pary + 2) * 4 + parx;
#pragma unroll
            for (int i = 0; i < 32; i++) v = fmaf(si[i * 196 + off], sw[i * 16 + kk], v); }
        if (vyb && vxb) { int off = iyb * 14 + ixb, kk = (pary + 2) * 4 + parx + 2;
#pragma unroll
            for (int i = 0; i < 32; i++) v = fmaf(si[i * 196 + off], sw[i * 16 + kk], v); }
        outp[b * 784 + idx] = __frcp_rn(__fadd_rn(1.f, __expf(-v)));
    }
    if (b == 0 && t == 0 && lossp) *lossp = (float)(1.2 * g_stats[ST_LOSS] / 200704.0);
}

// ---------------- host ----------------
template <typename... Args>
static void launch_pdl(void (*kern)(Args...), int grid, int block, Args... args) {
    cudaLaunchConfig_t cfg = {};
    cfg.gridDim = dim3(grid);
    cfg.blockDim = dim3(block);
    cfg.dynamicSmemBytes = 0;
    cfg.stream = 0;
    cudaLaunchAttribute attr[1];
    attr[0].id = cudaLaunchAttributeProgrammaticStreamSerialization;
    attr[0].val.programmaticStreamSerializationAllowed = 1;
    cfg.attrs = attr;
    cfg.numAttrs = 1;
    cudaLaunchKernelEx(&cfg, kern, args...);
}

extern "C" void kernel_launch(void* const* d_in, const int* in_sizes, int n_in,
                              void* d_out, int out_size) {
    const float* x    = (const float*)d_in[0];
    const float* ew1  = (const float*)d_in[1];
    const float* eb1  = (const float*)d_in[2];
    const float* g1   = (const float*)d_in[3];
    const float* b1   = (const float*)d_in[4];
    const float* ew2  = (const float*)d_in[5];
    const float* eb2  = (const float*)d_in[6];
    const float* g2   = (const float*)d_in[7];
    const float* b2   = (const float*)d_in[8];
    const float* embed= (const float*)d_in[9];
    const float* dw1  = (const float*)d_in[10];
    const float* dbi1 = (const float*)d_in[11];
    const float* dg1  = (const float*)d_in[12];
    const float* dbb1 = (const float*)d_in[13];
    const float* dw2  = (const float*)d_in[14];
    const float* dbi2 = (const float*)d_in[15];
    const float* dg2  = (const float*)d_in[16];
    const float* dbb2 = (const float*)d_in[17];
    const float* tw1  = (const float*)d_in[18];
    const float* tbi1 = (const float*)d_in[19];
    const float* dg3  = (const float*)d_in[20];
    const float* dbb3 = (const float*)d_in[21];
    const float* tw2  = (const float*)d_in[22];
    const float* tbi2 = (const float*)d_in[23];

    const int OUT_IMG = NB * 784;     // 1605632
    const int OUT_CLS = NB * 49;      // 100352
    float* out = (float*)d_out;
    float* cls   = (out_size >= OUT_IMG + OUT_CLS) ? out + OUT_IMG : nullptr;
    float* lossp = (out_size >= OUT_IMG + OUT_CLS + 1) ? out + OUT_IMG + OUT_CLS : nullptr;

    k0_zero<<<1, 128>>>();
    launch_pdl(k1_conv1, NB, 224, x, ew1, eb1);
    launch_pdl(k2_conv2, NB, 224, ew2, eb2, g1, b1);
    launch_pdl(k3_vq, NB, 256, embed, g2, b2, dw1, dbi1, (float*)cls);
    launch_pdl(k4_dec2, NB, 128, dg1, dbb1, dw2, dbi2);
    launch_pdl(k5_convt1, NB, 224, dg2, dbb2, tw1, tbi1);
    launch_pdl(k6_convt2, NB, 256, dg3, dbb3, tw2, tbi2, (float*)out, (float*)lossp);
}

// round 17
// speedup vs baseline: 1.0083x; 1.0083x over previous
#include <cuda_runtime.h>
#include <math.h>

#define NB 2048
#define BN_EPS 1e-5

// ---- fp64 stats (encoder + loss) ----
#define ST1_SUM 0     // 16
#define ST1_SQ  16    // 16
#define ST2_SUM 32    // 2
#define ST2_SQ  34    // 2
#define ST_LOSS 36
#define ST_TOTAL 37
// ---- fp32 stats (decoder) ----
#define FH1_SUM 0   // 2
#define FH1_SQ  2   // 2
#define FH2_SUM 4   // 2
#define FH2_SQ  6   // 2
#define FY3_SUM 8   // 32
#define FY3_SQ  40  // 32
#define STF_TOTAL 72

// zero-initialized at module load (covers call #1); re-zeroed by the
// distributed scheme below for every subsequent call:
//   k1.b0 -> FY3 + ST_LOSS   (k1 never touches them; consumed by k5/k6, k3/k6)
//   k3.b0 -> ST1             (last read by k2)
//   k4.b0 -> ST2             (last read by k3)
//   k5.b0 -> FH1             (last read by k4)
//   k6.b0 -> FH2             (last read by k5)
__device__ double g_stats[ST_TOTAL];
__device__ float g_statsf[STF_TOTAL];
__device__ float g_y1[NB * 16 * 196];   // conv1 raw out (B,16,14,14)
__device__ float g_y2[NB * 98];         // conv2 raw out (B,2,7,7)
__device__ float g_h1[NB * 98];         // dec conv1 raw out
__device__ float g_h2[NB * 98];         // dec conv2 raw out
__device__ float g_y3[NB * 32 * 196];   // convT1 raw out (B,32,14,14) channel-major

// decoder BN coefficients from fp32 sums
__device__ __forceinline__ void bn_coef_f(float sum, float sq, double N,
                                          float g, float b, float* sc, float* sh) {
    double mu = (double)sum / N;
    double var = (double)sq / N - mu * mu;
    double s = (double)g / sqrt(var + BN_EPS);
    *sc = (float)s;
    *sh = (float)((double)b - mu * s);
}

// encoder BN: fp32 mu / var rounded once from exact fp64 stats; r via libdevice rsqrtf
__device__ __forceinline__ void bn_mur(double sum, double sq, double N,
                                       float* muf, float* rf) {
    double mu = sum / N;
    double var = sq / N - mu * mu;
    float vf = (float)var;
    *muf = (float)mu;
    *rf = rsqrtf(__fadd_rn(vf, 1e-5f));
}

// exact reference BN+ReLU: relu(((x - mu) * r) * g + b)
__device__ __forceinline__ float bn_ref(float x, float mu, float r, float g, float b) {
    float t = __fmul_rn(__fsub_rn(x, mu), r);
    return fmaxf(__fmaf_rn(t, g, b), 0.f);
}

// ---------------- K1: conv1 (1->16, 4x4, s2, p1), fp64-exact accumulation + fp64 stats ----------------
__global__ void __launch_bounds__(224) k1_conv1(const float* __restrict__ x,
                                                const float* __restrict__ w,
                                                const float* __restrict__ bias) {
    __shared__ float sx[784];
    __shared__ float sw[256];
    __shared__ float sb[16];
    __shared__ float ys[16 * 196];
    __shared__ double sA[16], sQ[16];
    int b = blockIdx.x, t = threadIdx.x;

    // re-zero stats consumed later this call (FY3, ST_LOSS); k1 never touches them
    if (b == 0) {
        if (t < 64) g_statsf[FY3_SUM + t] = 0.f;
        if (t == 64) g_stats[ST_LOSS] = 0.0;
    }

    for (int i = t; i < 784; i += 224) sx[i] = x[b * 784 + i];
    for (int i = t; i < 256; i += 224) sw[i] = w[i];
    if (t < 16) { sb[t] = bias[t]; sA[t] = 0.0; sQ[t] = 0.0; }
    __syncthreads();

    bool act = t < 196;
    int oy = act ? t / 14 : 0, ox = act ? t % 14 : 0;
    float win[16];
#pragma unroll
    for (int k = 0; k < 16; k++) win[k] = 0.f;
    if (act) {
#pragma unroll
        for (int ky = 0; ky < 4; ky++) {
            int iy = 2 * oy - 1 + ky;
#pragma unroll
            for (int kx = 0; kx < 4; kx++) {
                int ix = 2 * ox - 1 + kx;
                win[ky * 4 + kx] = (iy >= 0 && iy < 28 && ix >= 0 && ix < 28) ? sx[iy * 28 + ix] : 0.f;
            }
        }
    }
    if (act) {
        double dwin[16];
#pragma unroll
        for (int k = 0; k < 16; k++) dwin[k] = (double)win[k];
#pragma unroll
        for (int c = 0; c < 16; c++) {
            double s = 0.0;
#pragma unroll
            for (int k = 0; k < 16; k++) s = fma(dwin[k], (double)sw[c * 16 + k], s);
            float v = __fadd_rn((float)s, sb[c]);
            g_y1[(b * 16 + c) * 196 + t] = v;
            ys[c * 196 + t] = v;
        }
    }
    __syncthreads();

    {
        int ch = t / 14, sub = t % 14;
        const float* row = &ys[ch * 196 + sub * 14];
        double s = 0.0, s2 = 0.0;
#pragma unroll
        for (int i = 0; i < 14; i++) { double v = (double)row[i]; s += v; s2 = fma(v, v, s2); }
        atomicAdd(&sA[ch], s); atomicAdd(&sQ[ch], s2);
    }
    __syncthreads();
    if (t < 16) {
        atomicAdd(&g_stats[ST1_SUM + t], sA[t]);
        atomicAdd(&g_stats[ST1_SQ + t], sQ[t]);
    }
}

// ---------------- K2: BN1+ReLU -> conv2 (16->2) fp64-exact, split 2-way + fp64 stats ----------------
__global__ void __launch_bounds__(224) k2_conv2(const float* __restrict__ w2,
                                                const float* __restrict__ bias2,
                                                const float* __restrict__ g1,
                                                const float* __restrict__ b1) {
    __shared__ float s1[3136];
    __shared__ float sw[512];
    __shared__ float smu[16], sr[16], sg[16], sbb[16];
    __shared__ double psd[196];
    __shared__ double sA[2], sQ[2];
    int b = blockIdx.x, t = threadIdx.x;

    if (t < 16) {
        bn_mur(g_stats[ST1_SUM + t], g_stats[ST1_SQ + t], 401408.0, &smu[t], &sr[t]);
        sg[t] = g1[t]; sbb[t] = b1[t];
    }
    if (t < 2) { sA[t] = 0.0; sQ[t] = 0.0; }
    for (int i = t; i < 512; i += 224) sw[i] = w2[i];
    __syncthreads();

    for (int i = t; i < 3136; i += 224) {
        int c = i / 196;
        s1[i] = bn_ref(g_y1[b * 3136 + i], smu[c], sr[c], sg[c], sbb[c]);
    }
    __syncthreads();

    if (t < 196) {
        int half = t / 98, o = t % 98;
        int c = o / 49, p = o % 49, oy = p / 7, ox = p % 7;
        double s = 0.0;
#pragma unroll
        for (int ic8 = 0; ic8 < 8; ic8++) {
            int ic = half * 8 + ic8;
#pragma unroll
            for (int ky = 0; ky < 4; ky++) {
                int iy = 2 * oy - 1 + ky;
                if (iy < 0 || iy >= 14) continue;
#pragma unroll
                for (int kx = 0; kx < 4; kx++) {
                    int ix = 2 * ox - 1 + kx;
                    if (ix < 0 || ix >= 14) continue;
                    s = fma((double)s1[ic * 196 + iy * 14 + ix],
                            (double)sw[c * 256 + ic * 16 + ky * 4 + kx], s);
                }
            }
        }
        psd[t] = s;
    }
    __syncthreads();

    if (t < 98) {
        int c = t / 49;
        double sum = psd[t] + psd[t + 98];
        float v = __fadd_rn((float)sum, bias2[c]);
        g_y2[b * 98 + t] = v;
        atomicAdd(&sA[c], (double)v); atomicAdd(&sQ[c], (double)v * (double)v);
    }
    __syncthreads();
    if (t < 2) {
        atomicAdd(&g_stats[ST2_SUM + t], sA[t]);
        atomicAdd(&g_stats[ST2_SQ + t], sQ[t]);
    }
}

// ------- K3: BN2+ReLU -> VQ (float4 codebook, interleaved 4-way k split) -> dec conv1 + fp32 stats -------
__global__ void __launch_bounds__(256) k3_vq(const float* __restrict__ embed,
                                             const float* __restrict__ g2,
                                             const float* __restrict__ b2,
                                             const float* __restrict__ dw1,
                                             const float* __restrict__ dbi1,
                                             float* __restrict__ cls) {
    __shared__ float4 se4[512];
    __shared__ float sq[98], qt[98];
    __shared__ float smu[2], sr[2], sg[2], sbb[2];
    __shared__ float bd[196];
    __shared__ int bidx[196];
    __shared__ float sAf[2], sQf[2];
    __shared__ double sloss;
    int b = blockIdx.x, t = threadIdx.x;

    // re-zero ST1 for next call (last read by k2)
    if (b == 0 && t >= 128 && t < 160) g_stats[ST1_SUM + (t - 128)] = 0.0;

    if (t < 2) {
        bn_mur(g_stats[ST2_SUM + t], g_stats[ST2_SQ + t], 100352.0, &smu[t], &sr[t]);
        sg[t] = g2[t]; sbb[t] = b2[t];
        sAf[t] = 0.f; sQf[t] = 0.f;
    }
    if (t == 2) sloss = 0.0;
    const float2* emb2 = (const float2*)embed;
    for (int k = t; k < 512; k += 256) {
        float2 e = emb2[k];
        float ee = __fadd_rn(__fmul_rn(e.x, e.x), __fmul_rn(e.y, e.y));
        se4[k] = make_float4(e.x, e.y, ee, 0.f);
    }
    __syncthreads();   // BN coefs + codebook visible to all

    if (t < 98) {
        int c = t / 49;
        sq[t] = bn_ref(g_y2[b * 98 + t], smu[c], sr[c], sg[c], sbb[c]);
    }
    __syncthreads();

    if (t < 196) {
        int n = t >> 2, ch = t & 3;
        float q0 = sq[2 * n], q1 = sq[2 * n + 1];
        float qq = __fadd_rn(__fmul_rn(q0, q0), __fmul_rn(q1, q1));
        float best = 3.4e38f; int bi = ch;
#pragma unroll 4
        for (int j = 0; j < 128; j++) {
            int k = ch + 4 * j;
            float4 E = se4[k];
            float dot = __fmaf_rn(q1, E.y, __fmul_rn(q0, E.x));
            float d = __fsub_rn(__fadd_rn(qq, E.z), __fmul_rn(2.f, dot));
            if (d < best) { best = d; bi = k; }
        }
        bd[t] = best; bidx[t] = bi;
    }
    __syncthreads();

    if (t < 49) {
        float best = bd[4 * t]; int k = bidx[4 * t];
#pragma unroll
        for (int j = 1; j < 4; j++) {
            float d = bd[4 * t + j]; int kk = bidx[4 * t + j];
            if (d < best || (d == best && kk < k)) { best = d; k = kk; }
        }
        float4 E = se4[k];
        qt[2 * t] = E.x; qt[2 * t + 1] = E.y;
        if (cls) cls[b * 49 + t] = (float)k;
        float da = E.x - sq[2 * t], db = E.y - sq[2 * t + 1];
        atomicAdd(&sloss, (double)da * da + (double)db * db);
    }
    __syncthreads();

    if (t < 98) {
        int o = t / 49, p = t % 49;
        float v = fmaf(dw1[o * 2], qt[p], fmaf(dw1[o * 2 + 1], qt[49 + p], dbi1[o]));
        g_h1[b * 98 + t] = v;
        atomicAdd(&sAf[o], v); atomicAdd(&sQf[o], v * v);
    }
    __syncthreads();
    if (t < 2) {
        atomicAdd(&g_statsf[FH1_SUM + t], sAf[t]);
        atomicAdd(&g_statsf[FH1_SQ + t], sQf[t]);
    }
    if (t == 2) atomicAdd(&g_stats[ST_LOSS], sloss);
}

// ---------------- K4: BN(h1)+ReLU -> dec conv2 (1x1) + fp32 stats ----------------
__global__ void __launch_bounds__(128) k4_dec2(const float* __restrict__ dg1,
                                               const float* __restrict__ dbb1,
                                               const float* __restrict__ dw2,
                                               const float* __restrict__ dbi2) {
    __shared__ float hb[98];
    __shared__ float sc[2], sh[2], sAf[2], sQf[2];
    int b = blockIdx.x, t = threadIdx.x;

    // re-zero ST2 for next call (last read by k3)
    if (b == 0 && t >= 64 && t < 68) g_stats[ST2_SUM + (t - 64)] = 0.0;

    if (t < 2) {
        bn_coef_f(g_statsf[FH1_SUM + t], g_statsf[FH1_SQ + t], 100352.0,
                  dg1[t], dbb1[t], &sc[t], &sh[t]);
        sAf[t] = 0.f; sQf[t] = 0.f;
    }
    __syncthreads();
    if (t < 98) {
        int c = t / 49;
        hb[t] = fmaxf(fmaf(g_h1[b * 98 + t], sc[c], sh[c]), 0.f);
    }
    __syncthreads();
    if (t < 98) {
        int o = t / 49, p = t % 49;
        float v = fmaf(dw2[o * 2], hb[p], fmaf(dw2[o * 2 + 1], hb[49 + p], dbi2[o]));
        g_h2[b * 98 + t] = v;
        atomicAdd(&sAf[o], v); atomicAdd(&sQf[o], v * v);
    }
    __syncthreads();
    if (t < 2) {
        atomicAdd(&g_statsf[FH2_SUM + t], sAf[t]);
        atomicAdd(&g_statsf[FH2_SQ + t], sQf[t]);
    }
}

// ---------------- K5: BN(h2)+ReLU -> convT1 (2->32) + smem-staged fp32 stats ----------------
__global__ void __launch_bounds__(224) k5_convt1(const float* __restrict__ dg2,
                                                 const float* __restrict__ dbb2,
                                                 const float* __restrict__ tw1,
                                                 const float* __restrict__ tbi1) {
    __shared__ float si[98];
    __shared__ float sw[1024];
    __shared__ float sc[2], sh[2];
    __shared__ float ys[32 * 196];
    __shared__ float sAf[32], sQf[32];
    __shared__ float sb[32];
    int b = blockIdx.x, t = threadIdx.x;

    // re-zero FH1 for next call (last read by k4)
    if (b == 0 && t >= 64 && t < 68) g_statsf[FH1_SUM + (t - 64)] = 0.f;

    if (t < 2) {
        bn_coef_f(g_statsf[FH2_SUM + t], g_statsf[FH2_SQ + t], 100352.0,
                  dg2[t], dbb2[t], &sc[t], &sh[t]);
    }
    if (t < 32) { sAf[t] = 0.f; sQf[t] = 0.f; sb[t] = tbi1[t]; }
    for (int i = t; i < 1024; i += 224) sw[i] = tw1[i];
    __syncthreads();
    for (int i = t; i < 98; i += 224) {
        int c = i / 49;
        si[i] = fmaxf(fmaf(g_h2[b * 98 + i], sc[c], sh[c]), 0.f);
    }
    __syncthreads();

    if (t < 196) {
        int y = t / 14, x = t % 14;
        int pary = (y + 1) & 1, parx = (x + 1) & 1;
        int iya = (y + 1 - pary) >> 1, iyb = iya - 1;
        int ixa = (x + 1 - parx) >> 1, ixb = ixa - 1;
        bool vya = (iya < 7), vyb = (iyb >= 0);
        bool vxa = (ixa < 7), vxb = (ixb >= 0);
        int kk_aa = pary * 4 + parx,       off_aa = iya * 7 + ixa;
        int kk_ab = pary * 4 + parx + 2,   off_ab = iya * 7 + ixb;
        int kk_ba = (pary + 2) * 4 + parx, off_ba = iyb * 7 + ixa;
        int kk_bb = (pary + 2) * 4 + parx + 2, off_bb = iyb * 7 + ixb;
        bool c_aa = vya && vxa, c_ab = vya && vxb, c_ba = vyb && vxa, c_bb = vyb && vxb;

#pragma unroll 4
        for (int o = 0; o < 32; o++) {
            float v = sb[o];
            if (c_aa) { v = fmaf(si[off_aa], sw[o * 16 + kk_aa], v); v = fmaf(si[49 + off_aa], sw[512 + o * 16 + kk_aa], v); }
            if (c_ab) { v = fmaf(si[off_ab], sw[o * 16 + kk_ab], v); v = fmaf(si[49 + off_ab], sw[512 + o * 16 + kk_ab], v); }
            if (c_ba) { v = fmaf(si[off_ba], sw[o * 16 + kk_ba], v); v = fmaf(si[49 + off_ba], sw[512 + o * 16 + kk_ba], v); }
            if (c_bb) { v = fmaf(si[off_bb], sw[o * 16 + kk_bb], v); v = fmaf(si[49 + off_bb], sw[512 + o * 16 + kk_bb], v); }
            g_y3[(b * 32 + o) * 196 + t] = v;
            ys[o * 196 + t] = v;
        }
    }
    __syncthreads();

    {
        int ch = t / 7, sub = t % 7;
        float s = 0.f, s2 = 0.f;
        const float* row = &ys[ch * 196 + sub * 28];
#pragma unroll
        for (int i = 0; i < 28; i++) { float v = row[i]; s += v; s2 = fmaf(v, v, s2); }
        atomicAdd(&sAf[ch], s); atomicAdd(&sQf[ch], s2);
    }
    __syncthreads();
    if (t < 32) {
        atomicAdd(&g_statsf[FY3_SUM + t], sAf[t]);
        atomicAdd(&g_statsf[FY3_SQ + t], sQf[t]);
    }
}

// ---------------- K6: BN(y3)+ReLU -> convT2 (32->1) -> fast sigmoid ----------------
__global__ void __launch_bounds__(256) k6_convt2(const float* __restrict__ dg3,
                                                 const float* __restrict__ dbb3,
                                                 const float* __restrict__ tw2,
                                                 const float* __restrict__ tbi2,
                                                 float* __restrict__ outp,
                                                 float* __restrict__ lossp) {
    __shared__ float si[6272];
    __shared__ float sw[512];
    __shared__ float sc[32], sh[32];
    int b = blockIdx.x, t = threadIdx.x;

    // re-zero FH2 for next call (last read by k5)
    if (b == 0 && t >= 64 && t < 68) g_statsf[FH2_SUM + (t - 64)] = 0.f;

    if (t < 32) {
        bn_coef_f(g_statsf[FY3_SUM + t], g_statsf[FY3_SQ + t], 401408.0,
                  dg3[t], dbb3[t], &sc[t], &sh[t]);
    }
    for (int i = t; i < 512; i += 256) sw[i] = tw2[i];
    __syncthreads();
    for (int i = t; i < 6272; i += 256) {
        int c = i / 196;
        si[i] = fmaxf(fmaf(g_y3[b * 6272 + i], sc[c], sh[c]), 0.f);
    }
    __syncthreads();

    float bias = tbi2[0];
    for (int idx = t; idx < 784; idx += 256) {
        int y = idx / 28, x = idx % 28;
        int pary = (y + 1) & 1, parx = (x + 1) & 1;
        int iya = (y + 1 - pary) >> 1, iyb = iya - 1;
        int ixa = (x + 1 - parx) >> 1, ixb = ixa - 1;
        bool vya = iya < 14, vyb = iyb >= 0, vxa = ixa < 14, vxb = ixb >= 0;
        float v = bias;
        if (vya && vxa) { int off = iya * 14 + ixa, kk = pary * 4 + parx;
#pragma unroll
            for (int i = 0; i < 32; i++) v = fmaf(si[i * 196 + off], sw[i * 16 + kk], v); }
        if (vya && vxb) { int off = iya * 14 + ixb, kk = pary * 4 + parx + 2;
#pragma unroll
            for (int i = 0; i < 32; i++) v = fmaf(si[i * 196 + off], sw[i * 16 + kk], v); }
        if (vyb && vxa) { int off = iyb * 14 + ixa, kk = (pary + 2) * 4 + parx;
#pragma unroll
            for (int i = 0; i < 32; i++) v = fmaf(si[i * 196 + off], sw[i * 16 + kk], v); }
        if (vyb && vxb) { int off = iyb * 14 + ixb, kk = (pary + 2) * 4 + parx + 2;
#pragma unroll
            for (int i = 0; i < 32; i++) v = fmaf(si[i * 196 + off], sw[i * 16 + kk], v); }
        outp[b * 784 + idx] = __frcp_rn(__fadd_rn(1.f, __expf(-v)));
    }
    if (b == 0 && t == 0 && lossp) *lossp = (float)(1.2 * g_stats[ST_LOSS] / 200704.0);
}

// ---------------- host ----------------
extern "C" void kernel_launch(void* const* d_in, const int* in_sizes, int n_in,
                              void* d_out, int out_size) {
    const float* x    = (const float*)d_in[0];
    const float* ew1  = (const float*)d_in[1];
    const float* eb1  = (const float*)d_in[2];
    const float* g1   = (const float*)d_in[3];
    const float* b1   = (const float*)d_in[4];
    const float* ew2  = (const float*)d_in[5];
    const float* eb2  = (const float*)d_in[6];
    const float* g2   = (const float*)d_in[7];
    const float* b2   = (const float*)d_in[8];
    const float* embed= (const float*)d_in[9];
    const float* dw1  = (const float*)d_in[10];
    const float* dbi1 = (const float*)d_in[11];
    const float* dg1  = (const float*)d_in[12];
    const float* dbb1 = (const float*)d_in[13];
    const float* dw2  = (const float*)d_in[14];
    const float* dbi2 = (const float*)d_in[15];
    const float* dg2  = (const float*)d_in[16];
    const float* dbb2 = (const float*)d_in[17];
    const float* tw1  = (const float*)d_in[18];
    const float* tbi1 = (const float*)d_in[19];
    const float* dg3  = (const float*)d_in[20];
    const float* dbb3 = (const float*)d_in[21];
    const float* tw2  = (const float*)d_in[22];
    const float* tbi2 = (const float*)d_in[23];

    const int OUT_IMG = NB * 784;     // 1605632
    const int OUT_CLS = NB * 49;      // 100352
    float* out = (float*)d_out;
    float* cls   = (out_size >= OUT_IMG + OUT_CLS) ? out + OUT_IMG : nullptr;
    float* lossp = (out_size >= OUT_IMG + OUT_CLS + 1) ? out + OUT_IMG + OUT_CLS : nullptr;

    k1_conv1<<<NB, 224>>>(x, ew1, eb1);
    k2_conv2<<<NB, 224>>>(ew2, eb2, g1, b1);
    k3_vq<<<NB, 256>>>(embed, g2, b2, dw1, dbi1, cls);
    k4_dec2<<<NB, 128>>>(dg1, dbb1, dw2, dbi2);
    k5_convt1<<<NB, 224>>>(dg2, dbb2, tw1, tbi1);
    k6_convt2<<<NB, 256>>>(dg3, dbb3, tw2, tbi2, out, lossp);
}